// round 1
// baseline (speedup 1.0000x reference)
#include <cuda_runtime.h>

#define NB   4
#define CIN  256
#define NSP  2304      // 48*48 tokens
#define NH   8
#define HDIM 64
#define HB   32        // NH*NB
#define QK_SCALE 0.125f

// Scratch (device globals — no allocations allowed)
__device__ float g_q  [(size_t)HB * NSP * HDIM];
__device__ float g_k  [(size_t)HB * NSP * HDIM];
__device__ float g_v  [(size_t)HB * NSP * HDIM];
__device__ float g_wsr[(size_t)4 * 512 * NSP];   // scrambled ws: [b2][c][p]

// ---------------------------------------------------------------------------
// Kernel A: QKV projection.  out[hb][n][d] = sum_c W[h][d][c] * x[b][c][n]
// grid (36 ntile, 32 hb, 3 qkv), block 256
// ---------------------------------------------------------------------------
__global__ void qkv_kernel(const float* __restrict__ x,
                           const float* __restrict__ Wq,
                           const float* __restrict__ Wk,
                           const float* __restrict__ Wv) {
    __shared__ float Ws[64 * 64];   // [d][c]
    __shared__ float Xs[64 * 64];   // [c][n]

    const int n0 = blockIdx.x * 64;
    const int hb = blockIdx.y;
    const int m  = blockIdx.z;
    const int h  = hb >> 2, b = hb & 3;

    const float* W   = (m == 0 ? Wq : (m == 1 ? Wk : Wv)) + (size_t)h * HDIM * CIN;
    float*       out = (m == 0 ? g_q : (m == 1 ? g_k : g_v)) + (size_t)hb * NSP * HDIM;
    const float* xb  = x + (size_t)b * CIN * NSP;

    const int tid = threadIdx.x;
    const int ty = tid >> 4, tx = tid & 15;

    float acc[4][4] = {};

    for (int c0 = 0; c0 < CIN; c0 += 64) {
        #pragma unroll
        for (int ps = 0; ps < 4; ps++) {
            int row = ps * 16 + (tid >> 4);
            int c4  = (tid & 15);
            *(float4*)&Ws[row * 64 + c4 * 4] =
                *(const float4*)&W[(size_t)row * CIN + c0 + c4 * 4];
            *(float4*)&Xs[row * 64 + c4 * 4] =
                *(const float4*)&xb[(size_t)(c0 + row) * NSP + n0 + c4 * 4];
        }
        __syncthreads();

        #pragma unroll
        for (int k4 = 0; k4 < 16; k4++) {
            float4 a[4];
            #pragma unroll
            for (int i = 0; i < 4; i++)
                a[i] = *(float4*)&Ws[(ty * 4 + i) * 64 + k4 * 4];
            #pragma unroll
            for (int u = 0; u < 4; u++) {
                float4 bx = *(float4*)&Xs[(k4 * 4 + u) * 64 + tx * 4];
                #pragma unroll
                for (int i = 0; i < 4; i++) {
                    float av = ((const float*)&a[i])[u];
                    acc[i][0] += av * bx.x;
                    acc[i][1] += av * bx.y;
                    acc[i][2] += av * bx.z;
                    acc[i][3] += av * bx.w;
                }
            }
        }
        __syncthreads();
    }

    // out[n][d]: d contiguous → transpose micro-tile in registers, store float4
    #pragma unroll
    for (int j = 0; j < 4; j++) {
        float4 v = make_float4(acc[0][j], acc[1][j], acc[2][j], acc[3][j]);
        *(float4*)&out[(size_t)(n0 + tx * 4 + j) * HDIM + ty * 4] = v;
    }
}

// ---------------------------------------------------------------------------
// Kernel B: flash attention per (hb, q-tile of 64 rows), scatter epilogue.
// grid (36 qtile, 32 hb), block 256, 64KB dynamic smem
// ---------------------------------------------------------------------------
__global__ void attn_kernel() {
    extern __shared__ float smem[];
    float* Qs = smem;            // [n][d]
    float* KT = smem + 4096;     // [d][n]  (transposed)
    float* Vs = smem + 8192;     // [n][d]
    float* Ps = smem + 12288;    // [r][c]

    const int qt = blockIdx.x;
    const int hb = blockIdx.y;
    const int h = hb >> 2, b = hb & 3;

    const float* qg = g_q + (size_t)hb * NSP * HDIM;
    const float* kg = g_k + (size_t)hb * NSP * HDIM;
    const float* vg = g_v + (size_t)hb * NSP * HDIM;

    const int tid = threadIdx.x;
    const int ty = tid >> 4, tx = tid & 15;

    // Load Q tile [64][64]
    #pragma unroll
    for (int ps = 0; ps < 4; ps++) {
        int row = ps * 16 + (tid >> 4);
        int d4  = (tid & 15);
        *(float4*)&Qs[row * 64 + d4 * 4] =
            *(const float4*)&qg[(size_t)(qt * 64 + row) * HDIM + d4 * 4];
    }

    float mi[4], li[4], O[4][4];
    #pragma unroll
    for (int i = 0; i < 4; i++) {
        mi[i] = -1e30f; li[i] = 0.f;
        #pragma unroll
        for (int j = 0; j < 4; j++) O[i][j] = 0.f;
    }

    for (int kt = 0; kt < NSP / 64; kt++) {
        __syncthreads();   // prior PV reads of Ps/Vs, prior S reads of KT done
        #pragma unroll
        for (int ps = 0; ps < 4; ps++) {
            int nl = ps * 16 + (tid >> 4);
            int d4 = (tid & 15);
            float4 kv = *(const float4*)&kg[(size_t)(kt * 64 + nl) * HDIM + d4 * 4];
            KT[(d4 * 4 + 0) * 64 + nl] = kv.x;
            KT[(d4 * 4 + 1) * 64 + nl] = kv.y;
            KT[(d4 * 4 + 2) * 64 + nl] = kv.z;
            KT[(d4 * 4 + 3) * 64 + nl] = kv.w;
            *(float4*)&Vs[nl * 64 + d4 * 4] =
                *(const float4*)&vg[(size_t)(kt * 64 + nl) * HDIM + d4 * 4];
        }
        __syncthreads();

        // S = Q @ K^T  (4x4 per thread)
        float s[4][4] = {};
        #pragma unroll
        for (int k4 = 0; k4 < 16; k4++) {
            float4 a[4];
            #pragma unroll
            for (int i = 0; i < 4; i++)
                a[i] = *(float4*)&Qs[(ty * 4 + i) * 64 + k4 * 4];
            #pragma unroll
            for (int u = 0; u < 4; u++) {
                float4 bx = *(float4*)&KT[(k4 * 4 + u) * 64 + tx * 4];
                #pragma unroll
                for (int i = 0; i < 4; i++) {
                    float av = ((const float*)&a[i])[u];
                    s[i][0] += av * bx.x;
                    s[i][1] += av * bx.y;
                    s[i][2] += av * bx.z;
                    s[i][3] += av * bx.w;
                }
            }
        }

        // online softmax (row groups = 16 lanes within half-warp)
        #pragma unroll
        for (int i = 0; i < 4; i++) {
            #pragma unroll
            for (int j = 0; j < 4; j++) s[i][j] *= QK_SCALE;
            float tmax = fmaxf(fmaxf(s[i][0], s[i][1]), fmaxf(s[i][2], s[i][3]));
            #pragma unroll
            for (int off = 1; off < 16; off <<= 1)
                tmax = fmaxf(tmax, __shfl_xor_sync(0xffffffffu, tmax, off));
            float mn = fmaxf(mi[i], tmax);
            float alpha = __expf(mi[i] - mn);
            float rs = 0.f;
            #pragma unroll
            for (int j = 0; j < 4; j++) {
                s[i][j] = __expf(s[i][j] - mn);
                rs += s[i][j];
            }
            #pragma unroll
            for (int off = 1; off < 16; off <<= 1)
                rs += __shfl_xor_sync(0xffffffffu, rs, off);
            li[i] = li[i] * alpha + rs;
            mi[i] = mn;
            #pragma unroll
            for (int j = 0; j < 4; j++) O[i][j] *= alpha;
            *(float4*)&Ps[(ty * 4 + i) * 64 + tx * 4] =
                make_float4(s[i][0], s[i][1], s[i][2], s[i][3]);
        }
        __syncthreads();

        // O += P @ V
        #pragma unroll
        for (int k4 = 0; k4 < 16; k4++) {
            float4 p[4];
            #pragma unroll
            for (int i = 0; i < 4; i++)
                p[i] = *(float4*)&Ps[(ty * 4 + i) * 64 + k4 * 4];
            #pragma unroll
            for (int u = 0; u < 4; u++) {
                float4 bv = *(float4*)&Vs[(k4 * 4 + u) * 64 + tx * 4];
                #pragma unroll
                for (int i = 0; i < 4; i++) {
                    float pv = ((const float*)&p[i])[u];
                    O[i][0] += pv * bv.x;
                    O[i][1] += pv * bv.y;
                    O[i][2] += pv * bv.z;
                    O[i][3] += pv * bv.w;
                }
            }
        }
    }

    // Epilogue: normalize + scatter into scrambled layout.
    // ws[h,n,b,d] -> wsr[b2 = h>>1][c = (h&1)*256 + n/9][p = (n%9)*256 + b*64 + d]
    const int b2 = h >> 1;
    #pragma unroll
    for (int i = 0; i < 4; i++) {
        int n = qt * 64 + ty * 4 + i;
        float inv = 1.0f / li[i];
        int cch = ((h & 1) << 8) + n / 9;
        int p   = (n % 9) * 256 + b * 64 + tx * 4;
        *(float4*)&g_wsr[((size_t)(b2 * 512 + cch)) * NSP + p] =
            make_float4(O[i][0] * inv, O[i][1] * inv, O[i][2] * inv, O[i][3] * inv);
    }
}

// ---------------------------------------------------------------------------
// Kernel C: output projection. out[b2][o][p] = sum_c Wo[o][c] * wsr[b2][c][p]
// grid (36 ptile, 4 otile, 4 b2), block 256
// ---------------------------------------------------------------------------
__global__ void oproj_kernel(const float* __restrict__ Wo,
                             float* __restrict__ out) {
    __shared__ float Ws[64 * 64];   // [o][c]
    __shared__ float Xs[64 * 64];   // [c][p]

    const int p0 = blockIdx.x * 64;
    const int o0 = blockIdx.y * 64;
    const int b2 = blockIdx.z;
    const float* wsr = g_wsr + (size_t)b2 * 512 * NSP;

    const int tid = threadIdx.x;
    const int ty = tid >> 4, tx = tid & 15;

    float acc[4][4] = {};

    for (int c0 = 0; c0 < 512; c0 += 64) {
        #pragma unroll
        for (int ps = 0; ps < 4; ps++) {
            int row = ps * 16 + (tid >> 4);
            int c4  = (tid & 15);
            *(float4*)&Ws[row * 64 + c4 * 4] =
                *(const float4*)&Wo[(size_t)(o0 + row) * 512 + c0 + c4 * 4];
            *(float4*)&Xs[row * 64 + c4 * 4] =
                *(const float4*)&wsr[(size_t)(c0 + row) * NSP + p0 + c4 * 4];
        }
        __syncthreads();

        #pragma unroll
        for (int k4 = 0; k4 < 16; k4++) {
            float4 a[4];
            #pragma unroll
            for (int i = 0; i < 4; i++)
                a[i] = *(float4*)&Ws[(ty * 4 + i) * 64 + k4 * 4];
            #pragma unroll
            for (int u = 0; u < 4; u++) {
                float4 bx = *(float4*)&Xs[(k4 * 4 + u) * 64 + tx * 4];
                #pragma unroll
                for (int i = 0; i < 4; i++) {
                    float av = ((const float*)&a[i])[u];
                    acc[i][0] += av * bx.x;
                    acc[i][1] += av * bx.y;
                    acc[i][2] += av * bx.z;
                    acc[i][3] += av * bx.w;
                }
            }
        }
        __syncthreads();
    }

    #pragma unroll
    for (int i = 0; i < 4; i++) {
        *(float4*)&out[((size_t)(b2 * 256 + o0 + ty * 4 + i)) * NSP + p0 + tx * 4] =
            make_float4(acc[i][0], acc[i][1], acc[i][2], acc[i][3]);
    }
}

// ---------------------------------------------------------------------------
extern "C" void kernel_launch(void* const* d_in, const int* in_sizes, int n_in,
                              void* d_out, int out_size) {
    const float* x  = (const float*)d_in[0];
    const float* Wq = (const float*)d_in[1];
    const float* Wk = (const float*)d_in[2];
    const float* Wv = (const float*)d_in[3];
    const float* Wo = (const float*)d_in[4];
    float* out = (float*)d_out;

    cudaFuncSetAttribute(attn_kernel,
                         cudaFuncAttributeMaxDynamicSharedMemorySize, 65536);

    dim3 blk(256);
    qkv_kernel<<<dim3(NSP / 64, HB, 3), blk>>>(x, Wq, Wk, Wv);
    attn_kernel<<<dim3(NSP / 64, HB), blk, 65536>>>();
    oproj_kernel<<<dim3(NSP / 64, 4, 4), blk>>>(Wo, out);
}